// round 3
// baseline (speedup 1.0000x reference)
#include <cuda_runtime.h>

#define CIN   128
#define CTOT  128   // mu(64) | logstd(64) fused
#define COUT  64
#define MAXN  100000
#define MAX_LOGSTD 10.0f

// ---- scratch (static device allocations; runtime alloc is forbidden) ----
// float4-typed => guaranteed 16B alignment for LDG.128 / red.v4.f32
__device__ int    g_idx64;                              // 1 if edge_index is int64
__device__ int    g_deg[MAXN];
__device__ float  g_dinv[MAXN];
__device__ float4 g_g4  [(size_t)MAXN * (CTOT / 4)];    // h * dinv[n] (gather source)
__device__ float4 g_acc4[(size_t)MAXN * (CTOT / 4)];    // seeded with g (self-loop)

// ------------------------------------------------------- dtype detection ----
// If edge_index is真int64, every 8-byte value is in [0, N). If it is int32,
// an 8-byte read is lo + hi*2^32 with hi a random node id (≈ never all zero
// across 16 samples). Deterministic, recomputed every call.
__global__ void k_detect(const void* __restrict__ ei, int N) {
    if (threadIdx.x != 0 || blockIdx.x != 0) return;
    const long long* p = (const long long*)ei;
    int is64 = 1;
    #pragma unroll
    for (int i = 0; i < 16; i++) {
        long long v = p[i];
        if (v < 0 || v >= (long long)N) { is64 = 0; break; }
    }
    g_idx64 = is64;
}

__device__ __forceinline__ int load_idx(const void* __restrict__ base, long long i) {
    return g_idx64 ? (int)((const long long*)base)[i] : ((const int*)base)[i];
}

// ---------------------------------------------------------------- degree ----
__global__ void k_deg_init(int N) {
    int i = blockIdx.x * blockDim.x + threadIdx.x;
    if (i < N) g_deg[i] = 1;                    // self-loop
}

__global__ void k_deg(const void* __restrict__ ei, int E) {
    int i = blockIdx.x * blockDim.x + threadIdx.x;
    if (i < E) {
        int d = load_idx(ei, (long long)E + i);   // dst = second row
        atomicAdd(&g_deg[d], 1);
    }
}

__global__ void k_dinv(int N) {
    int i = blockIdx.x * blockDim.x + threadIdx.x;
    if (i < N) g_dinv[i] = rsqrtf((float)g_deg[i]);
}

// ------------------------------------------------------------------ GEMM ----
// h[n,0:64] = x[n,:] @ W_mu ; h[n,64:128] = x[n,:] @ W_ls ; g = h * dinv[n]
// Tile: 64 rows x 128 cols. K tiled by 32. 256 threads: 4 rows x 8 cols each.
#define BM 64
#define BK 32

__global__ __launch_bounds__(256)
void k_gemm(const float* __restrict__ x,
            const float* __restrict__ Wmu,
            const float* __restrict__ Wls, int N) {
    __shared__ float As[BM][BK + 1];   // +1 pad: conflict-free column reads
    __shared__ float Ws[BK][CTOT];

    const int tid = threadIdx.x;
    const int n0  = blockIdx.x * BM;
    const int c0  = (tid & 15) * 8;    // 16 col-groups * 8 cols
    const int r0  = (tid >> 4) * 4;    // 16 row-groups * 4 rows

    float acc[4][8];
    #pragma unroll
    for (int i = 0; i < 4; i++)
        #pragma unroll
        for (int j = 0; j < 8; j++) acc[i][j] = 0.f;

    for (int kt = 0; kt < CIN; kt += BK) {
        // x tile: BM rows x BK cols = 512 float4
        for (int idx = tid; idx < BM * (BK / 4); idx += 256) {
            int r = idx >> 3, j = idx & 7;
            int n = n0 + r;
            float4 v = (n < N)
                ? __ldg((const float4*)(x + (size_t)n * CIN + kt) + j)
                : make_float4(0.f, 0.f, 0.f, 0.f);
            As[r][j * 4 + 0] = v.x; As[r][j * 4 + 1] = v.y;
            As[r][j * 4 + 2] = v.z; As[r][j * 4 + 3] = v.w;
        }
        // W tile: Ws[kk][0:64]=W_mu[kt+kk][:], Ws[kk][64:128]=W_ls[kt+kk][:]
        for (int idx = tid; idx < BK * 32; idx += 256) {       // 1024 float4
            int kk = idx >> 5, j = idx & 31;
            float4 v = (j < 16) ? __ldg((const float4*)Wmu + (kt + kk) * 16 + j)
                                : __ldg((const float4*)Wls + (kt + kk) * 16 + (j - 16));
            *(float4*)&Ws[kk][j * 4] = v;
        }
        __syncthreads();

        #pragma unroll 8
        for (int kk = 0; kk < BK; kk++) {
            float a0 = As[r0 + 0][kk], a1 = As[r0 + 1][kk];
            float a2 = As[r0 + 2][kk], a3 = As[r0 + 3][kk];
            float4 w0 = *(float4*)&Ws[kk][c0];
            float4 w1 = *(float4*)&Ws[kk][c0 + 4];
            float w[8] = {w0.x, w0.y, w0.z, w0.w, w1.x, w1.y, w1.z, w1.w};
            #pragma unroll
            for (int j = 0; j < 8; j++) {
                acc[0][j] += a0 * w[j];
                acc[1][j] += a1 * w[j];
                acc[2][j] += a2 * w[j];
                acc[3][j] += a3 * w[j];
            }
        }
        __syncthreads();
    }

    #pragma unroll
    for (int i = 0; i < 4; i++) {
        int n = n0 + r0 + i;
        if (n >= N) continue;
        float di = g_dinv[n];
        float4 v0, v1;
        v0.x = acc[i][0] * di; v0.y = acc[i][1] * di;
        v0.z = acc[i][2] * di; v0.w = acc[i][3] * di;
        v1.x = acc[i][4] * di; v1.y = acc[i][5] * di;
        v1.z = acc[i][6] * di; v1.w = acc[i][7] * di;
        size_t off = (size_t)n * (CTOT / 4) + (c0 >> 2);
        g_g4  [off]     = v0;  g_g4  [off + 1] = v1;
        g_acc4[off]     = v0;  g_acc4[off + 1] = v1;
    }
}

// --------------------------------------------------------------- scatter ----
// warp per edge: lane L moves float4 #L of the 128-float (32-float4) row.
__global__ __launch_bounds__(256)
void k_scatter(const void* __restrict__ ei, int E) {
    int lane = threadIdx.x & 31;
    int w    = (blockIdx.x * blockDim.x + threadIdx.x) >> 5;
    if (w >= E) return;
    int s = load_idx(ei, w);
    int d = load_idx(ei, (long long)E + w);
    float4 v = __ldg(&g_g4[(size_t)s * 32 + lane]);
    float* p = (float*)&g_acc4[(size_t)d * 32 + lane];
    asm volatile("red.global.add.v4.f32 [%0], {%1,%2,%3,%4};"
                 :: "l"(p), "f"(v.x), "f"(v.y), "f"(v.z), "f"(v.w) : "memory");
}

// -------------------------------------------------------------- finalize ----
// z[n,c] = (dinv*acc_mu + b_mu) + eps * exp(min(dinv*acc_ls + b_ls, 10))
__global__ __launch_bounds__(256)
void k_final(const float* __restrict__ bmu, const float* __restrict__ bls,
             const float* __restrict__ eps, float* __restrict__ out, int N) {
    int i = blockIdx.x * blockDim.x + threadIdx.x;   // over N*16 float4-groups
    if (i >= N * 16) return;
    int n = i >> 4, q = i & 15;
    float di = g_dinv[n];
    float4 am = g_acc4[(size_t)n * 32 + q];
    float4 al = g_acc4[(size_t)n * 32 + 16 + q];
    float4 bm = __ldg((const float4*)bmu + q);
    float4 bl = __ldg((const float4*)bls + q);
    float4 ep = __ldg((const float4*)(eps + (size_t)n * COUT) + q);
    float4 z;
    z.x = (am.x * di + bm.x) + ep.x * __expf(fminf(al.x * di + bl.x, MAX_LOGSTD));
    z.y = (am.y * di + bm.y) + ep.y * __expf(fminf(al.y * di + bl.y, MAX_LOGSTD));
    z.z = (am.z * di + bm.z) + ep.z * __expf(fminf(al.z * di + bl.z, MAX_LOGSTD));
    z.w = (am.w * di + bm.w) + ep.w * __expf(fminf(al.w * di + bl.w, MAX_LOGSTD));
    ((float4*)(out + (size_t)n * COUT))[q] = z;
}

// ---------------------------------------------------------------- launch ----
extern "C" void kernel_launch(void* const* d_in, const int* in_sizes, int n_in,
                              void* d_out, int out_size) {
    const float* x   = (const float*)d_in[0];
    const void*  ei  = d_in[1];                         // [2, E] int32 OR int64
    const float* Wmu = (const float*)d_in[2];
    const float* bmu = (const float*)d_in[3];
    const float* Wls = (const float*)d_in[4];
    const float* bls = (const float*)d_in[5];
    const float* eps = (const float*)d_in[6];
    float*       out = (float*)d_out;

    const int N = in_sizes[0] / CIN;
    const int E = in_sizes[1] / 2;

    k_detect  <<<1, 32>>>(ei, N);
    k_deg_init<<<(N + 255) / 256, 256>>>(N);
    k_deg     <<<(E + 255) / 256, 256>>>(ei, E);
    k_dinv    <<<(N + 255) / 256, 256>>>(N);
    k_gemm    <<<(N + BM - 1) / BM, 256>>>(x, Wmu, Wls, N);
    {
        long long threads = (long long)E * 32;
        int blocks = (int)((threads + 255) / 256);
        k_scatter <<<blocks, 256>>>(ei, E);
    }
    k_final   <<<(N * 16 + 255) / 256, 256>>>(bmu, bls, eps, out, N);
}

// round 4
// speedup vs baseline: 1.0141x; 1.0141x over previous
#include <cuda_runtime.h>

#define CIN   128
#define CTOT  128   // mu(64) | logstd(64) fused
#define COUT  64
#define MAXN  100000
#define MAX_LOGSTD 10.0f

// ---- scratch (static device allocations; runtime alloc is forbidden) ----
// float4-typed => guaranteed 16B alignment for LDG.128 / red.v4.f32
__device__ int    g_idx64;                              // 1 if edge_index is int64
__device__ int    g_deg[MAXN];
__device__ float  g_dinv[MAXN];
__device__ float4 g_g4  [(size_t)MAXN * (CTOT / 4)];    // h * dinv[n] (gather source)
__device__ float4 g_acc4[(size_t)MAXN * (CTOT / 4)];    // seeded with g (self-loop)

// ------------------------------------------------------- dtype detection ----
// If edge_index is真int64, every 8-byte value is in [0, N). If it is int32,
// an 8-byte read is lo + hi*2^32 with hi a random node id (≈ never all zero
// across 16 samples). Deterministic, recomputed every call.
__global__ void k_detect(const void* __restrict__ ei, int N) {
    if (threadIdx.x != 0 || blockIdx.x != 0) return;
    const long long* p = (const long long*)ei;
    int is64 = 1;
    #pragma unroll
    for (int i = 0; i < 16; i++) {
        long long v = p[i];
        if (v < 0 || v >= (long long)N) { is64 = 0; break; }
    }
    g_idx64 = is64;
}

__device__ __forceinline__ int load_idx(const void* __restrict__ base, long long i) {
    return g_idx64 ? (int)((const long long*)base)[i] : ((const int*)base)[i];
}

// ---------------------------------------------------------------- degree ----
__global__ void k_deg_init(int N) {
    int i = blockIdx.x * blockDim.x + threadIdx.x;
    if (i < N) g_deg[i] = 1;                    // self-loop
}

__global__ void k_deg(const void* __restrict__ ei, int E) {
    int i = blockIdx.x * blockDim.x + threadIdx.x;
    if (i < E) {
        int d = load_idx(ei, (long long)E + i);   // dst = second row
        atomicAdd(&g_deg[d], 1);
    }
}

__global__ void k_dinv(int N) {
    int i = blockIdx.x * blockDim.x + threadIdx.x;
    if (i < N) g_dinv[i] = rsqrtf((float)g_deg[i]);
}

// ------------------------------------------------------------------ GEMM ----
// h[n,0:64] = x[n,:] @ W_mu ; h[n,64:128] = x[n,:] @ W_ls ; g = h * dinv[n]
// Tile: 64 rows x 128 cols. K tiled by 32. 256 threads: 4 rows x 8 cols each.
#define BM 64
#define BK 32

__global__ __launch_bounds__(256)
void k_gemm(const float* __restrict__ x,
            const float* __restrict__ Wmu,
            const float* __restrict__ Wls, int N) {
    __shared__ float As[BM][BK + 1];   // +1 pad: conflict-free column reads
    __shared__ float Ws[BK][CTOT];

    const int tid = threadIdx.x;
    const int n0  = blockIdx.x * BM;
    const int c0  = (tid & 15) * 8;    // 16 col-groups * 8 cols
    const int r0  = (tid >> 4) * 4;    // 16 row-groups * 4 rows

    float acc[4][8];
    #pragma unroll
    for (int i = 0; i < 4; i++)
        #pragma unroll
        for (int j = 0; j < 8; j++) acc[i][j] = 0.f;

    for (int kt = 0; kt < CIN; kt += BK) {
        // x tile: BM rows x BK cols = 512 float4
        for (int idx = tid; idx < BM * (BK / 4); idx += 256) {
            int r = idx >> 3, j = idx & 7;
            int n = n0 + r;
            float4 v = (n < N)
                ? __ldg((const float4*)(x + (size_t)n * CIN + kt) + j)
                : make_float4(0.f, 0.f, 0.f, 0.f);
            As[r][j * 4 + 0] = v.x; As[r][j * 4 + 1] = v.y;
            As[r][j * 4 + 2] = v.z; As[r][j * 4 + 3] = v.w;
        }
        // W tile: Ws[kk][0:64]=W_mu[kt+kk][:], Ws[kk][64:128]=W_ls[kt+kk][:]
        for (int idx = tid; idx < BK * 32; idx += 256) {       // 1024 float4
            int kk = idx >> 5, j = idx & 31;
            float4 v = (j < 16) ? __ldg((const float4*)Wmu + (kt + kk) * 16 + j)
                                : __ldg((const float4*)Wls + (kt + kk) * 16 + (j - 16));
            *(float4*)&Ws[kk][j * 4] = v;
        }
        __syncthreads();

        #pragma unroll 8
        for (int kk = 0; kk < BK; kk++) {
            float a0 = As[r0 + 0][kk], a1 = As[r0 + 1][kk];
            float a2 = As[r0 + 2][kk], a3 = As[r0 + 3][kk];
            float4 w0 = *(float4*)&Ws[kk][c0];
            float4 w1 = *(float4*)&Ws[kk][c0 + 4];
            float w[8] = {w0.x, w0.y, w0.z, w0.w, w1.x, w1.y, w1.z, w1.w};
            #pragma unroll
            for (int j = 0; j < 8; j++) {
                acc[0][j] += a0 * w[j];
                acc[1][j] += a1 * w[j];
                acc[2][j] += a2 * w[j];
                acc[3][j] += a3 * w[j];
            }
        }
        __syncthreads();
    }

    #pragma unroll
    for (int i = 0; i < 4; i++) {
        int n = n0 + r0 + i;
        if (n >= N) continue;
        float di = g_dinv[n];
        float4 v0, v1;
        v0.x = acc[i][0] * di; v0.y = acc[i][1] * di;
        v0.z = acc[i][2] * di; v0.w = acc[i][3] * di;
        v1.x = acc[i][4] * di; v1.y = acc[i][5] * di;
        v1.z = acc[i][6] * di; v1.w = acc[i][7] * di;
        size_t off = (size_t)n * (CTOT / 4) + (c0 >> 2);
        g_g4  [off]     = v0;  g_g4  [off + 1] = v1;
        g_acc4[off]     = v0;  g_acc4[off + 1] = v1;
    }
}

// --------------------------------------------------------------- scatter ----
// warp per edge: lane L moves float4 #L of the 128-float (32-float4) row.
__global__ __launch_bounds__(256)
void k_scatter(const void* __restrict__ ei, int E) {
    int lane = threadIdx.x & 31;
    int w    = (blockIdx.x * blockDim.x + threadIdx.x) >> 5;
    if (w >= E) return;
    int s = load_idx(ei, w);
    int d = load_idx(ei, (long long)E + w);
    float4 v = __ldg(&g_g4[(size_t)s * 32 + lane]);
    float* p = (float*)&g_acc4[(size_t)d * 32 + lane];
    asm volatile("red.global.add.v4.f32 [%0], {%1,%2,%3,%4};"
                 :: "l"(p), "f"(v.x), "f"(v.y), "f"(v.z), "f"(v.w) : "memory");
}

// -------------------------------------------------------------- finalize ----
// z[n,c] = (dinv*acc_mu + b_mu) + eps * exp(min(dinv*acc_ls + b_ls, 10))
__global__ __launch_bounds__(256)
void k_final(const float* __restrict__ bmu, const float* __restrict__ bls,
             const float* __restrict__ eps, float* __restrict__ out, int N) {
    int i = blockIdx.x * blockDim.x + threadIdx.x;   // over N*16 float4-groups
    if (i >= N * 16) return;
    int n = i >> 4, q = i & 15;
    float di = g_dinv[n];
    float4 am = g_acc4[(size_t)n * 32 + q];
    float4 al = g_acc4[(size_t)n * 32 + 16 + q];
    float4 bm = __ldg((const float4*)bmu + q);
    float4 bl = __ldg((const float4*)bls + q);
    float4 ep = __ldg((const float4*)(eps + (size_t)n * COUT) + q);
    float4 z;
    z.x = (am.x * di + bm.x) + ep.x * __expf(fminf(al.x * di + bl.x, MAX_LOGSTD));
    z.y = (am.y * di + bm.y) + ep.y * __expf(fminf(al.y * di + bl.y, MAX_LOGSTD));
    z.z = (am.z * di + bm.z) + ep.z * __expf(fminf(al.z * di + bl.z, MAX_LOGSTD));
    z.w = (am.w * di + bm.w) + ep.w * __expf(fminf(al.w * di + bl.w, MAX_LOGSTD));
    ((float4*)(out + (size_t)n * COUT))[q] = z;
}

// ---------------------------------------------------------------- launch ----
extern "C" void kernel_launch(void* const* d_in, const int* in_sizes, int n_in,
                              void* d_out, int out_size) {
    const float* x   = (const float*)d_in[0];
    const void*  ei  = d_in[1];                         // [2, E] int32 OR int64
    const float* Wmu = (const float*)d_in[2];
    const float* bmu = (const float*)d_in[3];
    const float* Wls = (const float*)d_in[4];
    const float* bls = (const float*)d_in[5];
    const float* eps = (const float*)d_in[6];
    float*       out = (float*)d_out;

    const int N = in_sizes[0] / CIN;
    const int E = in_sizes[1] / 2;

    k_detect  <<<1, 32>>>(ei, N);
    k_deg_init<<<(N + 255) / 256, 256>>>(N);
    k_deg     <<<(E + 255) / 256, 256>>>(ei, E);
    k_dinv    <<<(N + 255) / 256, 256>>>(N);
    k_gemm    <<<(N + BM - 1) / BM, 256>>>(x, Wmu, Wls, N);
    {
        long long threads = (long long)E * 32;
        int blocks = (int)((threads + 255) / 256);
        k_scatter <<<blocks, 256>>>(ei, E);
    }
    k_final   <<<(N * 16 + 255) / 256, 256>>>(bmu, bls, eps, out, N);
}

// round 5
// speedup vs baseline: 1.4992x; 1.4783x over previous
#include <cuda_runtime.h>

#define CIN   128
#define CTOT  128   // mu(64) | logstd(64) fused
#define COUT  64
#define MAXN  100000
#define MAXE  3200000
#define MAX_LOGSTD 10.0f

// ---- scratch (static device allocs; runtime alloc is forbidden) ----
__device__ int    g_idx64;                              // 1 if edge_index is int64
__device__ int    g_ecnt[MAXN];                         // in-degree (edges only)
__device__ int    g_off [MAXN + 1];                     // CSR row offsets
__device__ int    g_cur [MAXN];                         // fill cursors
__device__ int    g_part[1024];                         // block partial sums
__device__ int    g_csr [MAXE];                         // CSR src ids
__device__ float  g_dinv[MAXN];
__device__ float4 g_g4  [(size_t)MAXN * (CTOT / 4)];    // h * dinv[n]

// ------------------------------------------------------- dtype detection ----
__global__ void k_detect(const void* __restrict__ ei, int N) {
    if (threadIdx.x != 0 || blockIdx.x != 0) return;
    const long long* p = (const long long*)ei;
    int is64 = 1;
    #pragma unroll
    for (int i = 0; i < 16; i++) {
        long long v = p[i];
        if (v < 0 || v >= (long long)N) { is64 = 0; break; }
    }
    g_idx64 = is64;
}

__device__ __forceinline__ int load_idx(const void* __restrict__ base, long long i) {
    return g_idx64 ? (int)((const long long*)base)[i] : ((const int*)base)[i];
}

// ---------------------------------------------------- degree + CSR build ----
__global__ void k_ecnt_init(int N) {
    int i = blockIdx.x * blockDim.x + threadIdx.x;
    if (i < N) g_ecnt[i] = 0;
}

__global__ void k_ecnt(const void* __restrict__ ei, int E) {
    int i = blockIdx.x * blockDim.x + threadIdx.x;
    if (i < E) atomicAdd(&g_ecnt[load_idx(ei, (long long)E + i)], 1);
}

// block partial sums over 256-element chunks
__global__ void k_bsum(int N) {
    __shared__ int s[256];
    int i = blockIdx.x * 256 + threadIdx.x;
    s[threadIdx.x] = (i < N) ? g_ecnt[i] : 0;
    __syncthreads();
    for (int st = 128; st > 0; st >>= 1) {
        if (threadIdx.x < st) s[threadIdx.x] += s[threadIdx.x + st];
        __syncthreads();
    }
    if (threadIdx.x == 0) g_part[blockIdx.x] = s[0];
}

// exclusive scan of <=1024 partials, single block
__global__ void k_pscan(int nb) {
    __shared__ int s[1024];
    int t = threadIdx.x;
    s[t] = (t < nb) ? g_part[t] : 0;
    __syncthreads();
    for (int st = 1; st < 1024; st <<= 1) {
        int v = (t >= st) ? s[t - st] : 0;
        __syncthreads();
        s[t] += v;
        __syncthreads();
    }
    if (t < nb) g_part[t] = (t == 0) ? 0 : s[t - 1];   // exclusive
}

// row offsets + cursors + dinv (intra-block exclusive scan + block base)
__global__ void k_offsets(int N, int E) {
    __shared__ int s[256];
    int i = blockIdx.x * 256 + threadIdx.x;
    int t = threadIdx.x;
    int c = (i < N) ? g_ecnt[i] : 0;
    s[t] = c;
    __syncthreads();
    for (int st = 1; st < 256; st <<= 1) {
        int v = (t >= st) ? s[t - st] : 0;
        __syncthreads();
        s[t] += v;
        __syncthreads();
    }
    if (i < N) {
        int off = g_part[blockIdx.x] + s[t] - c;   // exclusive
        g_off[i] = off;
        g_cur[i] = off;
        g_dinv[i] = rsqrtf((float)(1 + c));        // +1 self-loop
        if (i == N - 1) g_off[N] = E;
    }
}

__global__ void k_fill(const void* __restrict__ ei, int E) {
    int i = blockIdx.x * blockDim.x + threadIdx.x;
    if (i < E) {
        int sN = load_idx(ei, i);
        int d  = load_idx(ei, (long long)E + i);
        int slot = atomicAdd(&g_cur[d], 1);
        g_csr[slot] = sN;
    }
}

// ------------------------------------------------------------------ GEMM ----
// g[n,0:64] = (x[n,:] @ W_mu)*dinv[n]; g[n,64:128] = (x[n,:] @ W_ls)*dinv[n]
#define BM 64
#define BK 32

__global__ __launch_bounds__(256)
void k_gemm(const float* __restrict__ x,
            const float* __restrict__ Wmu,
            const float* __restrict__ Wls, int N) {
    __shared__ float As[BM][BK + 1];
    __shared__ float Ws[BK][CTOT];

    const int tid = threadIdx.x;
    const int n0  = blockIdx.x * BM;
    const int c0  = (tid & 15) * 8;
    const int r0  = (tid >> 4) * 4;

    float acc[4][8];
    #pragma unroll
    for (int i = 0; i < 4; i++)
        #pragma unroll
        for (int j = 0; j < 8; j++) acc[i][j] = 0.f;

    for (int kt = 0; kt < CIN; kt += BK) {
        for (int idx = tid; idx < BM * (BK / 4); idx += 256) {
            int r = idx >> 3, j = idx & 7;
            int n = n0 + r;
            float4 v = (n < N)
                ? __ldg((const float4*)(x + (size_t)n * CIN + kt) + j)
                : make_float4(0.f, 0.f, 0.f, 0.f);
            As[r][j * 4 + 0] = v.x; As[r][j * 4 + 1] = v.y;
            As[r][j * 4 + 2] = v.z; As[r][j * 4 + 3] = v.w;
        }
        for (int idx = tid; idx < BK * 32; idx += 256) {
            int kk = idx >> 5, j = idx & 31;
            float4 v = (j < 16) ? __ldg((const float4*)Wmu + (kt + kk) * 16 + j)
                                : __ldg((const float4*)Wls + (kt + kk) * 16 + (j - 16));
            *(float4*)&Ws[kk][j * 4] = v;
        }
        __syncthreads();

        #pragma unroll 8
        for (int kk = 0; kk < BK; kk++) {
            float a0 = As[r0 + 0][kk], a1 = As[r0 + 1][kk];
            float a2 = As[r0 + 2][kk], a3 = As[r0 + 3][kk];
            float4 w0 = *(float4*)&Ws[kk][c0];
            float4 w1 = *(float4*)&Ws[kk][c0 + 4];
            float w[8] = {w0.x, w0.y, w0.z, w0.w, w1.x, w1.y, w1.z, w1.w};
            #pragma unroll
            for (int j = 0; j < 8; j++) {
                acc[0][j] += a0 * w[j];
                acc[1][j] += a1 * w[j];
                acc[2][j] += a2 * w[j];
                acc[3][j] += a3 * w[j];
            }
        }
        __syncthreads();
    }

    #pragma unroll
    for (int i = 0; i < 4; i++) {
        int n = n0 + r0 + i;
        if (n >= N) continue;
        float di = g_dinv[n];
        float4 v0, v1;
        v0.x = acc[i][0] * di; v0.y = acc[i][1] * di;
        v0.z = acc[i][2] * di; v0.w = acc[i][3] * di;
        v1.x = acc[i][4] * di; v1.y = acc[i][5] * di;
        v1.z = acc[i][6] * di; v1.w = acc[i][7] * di;
        size_t off = (size_t)n * 32 + (c0 >> 2);
        g_g4[off] = v0;  g_g4[off + 1] = v1;
    }
}

// --------------------------------------- aggregate + finalize (warp/node) ----
// lane L owns float4 #L of the 128-wide row. lanes 0-15: mu, 16-31: logstd.
// z = (acc_mu*di + b_mu) + eps * exp(min(acc_ls*di + b_ls, 10))
__global__ __launch_bounds__(256)
void k_agg(const float* __restrict__ bmu, const float* __restrict__ bls,
           const float* __restrict__ eps, float* __restrict__ out, int N) {
    int lane = threadIdx.x & 31;
    int d    = (blockIdx.x * blockDim.x + threadIdx.x) >> 5;
    if (d >= N) return;

    float4 a = g_g4[(size_t)d * 32 + lane];        // self-loop seed
    int j   = g_off[d];
    int end = g_off[d + 1];

    for (; j + 1 < end; j += 2) {                  // unroll x2 for MLP
        int s0 = g_csr[j], s1 = g_csr[j + 1];
        float4 v0 = __ldg(&g_g4[(size_t)s0 * 32 + lane]);
        float4 v1 = __ldg(&g_g4[(size_t)s1 * 32 + lane]);
        a.x += v0.x + v1.x; a.y += v0.y + v1.y;
        a.z += v0.z + v1.z; a.w += v0.w + v1.w;
    }
    if (j < end) {
        float4 v = __ldg(&g_g4[(size_t)g_csr[j] * 32 + lane]);
        a.x += v.x; a.y += v.y; a.z += v.z; a.w += v.w;
    }

    float di = g_dinv[d];
    float4 b = (lane < 16) ? __ldg((const float4*)bmu + lane)
                           : __ldg((const float4*)bls + (lane - 16));
    float4 t;
    t.x = a.x * di + b.x; t.y = a.y * di + b.y;
    t.z = a.z * di + b.z; t.w = a.w * di + b.w;
    if (lane >= 16) {
        t.x = __expf(fminf(t.x, MAX_LOGSTD));
        t.y = __expf(fminf(t.y, MAX_LOGSTD));
        t.z = __expf(fminf(t.z, MAX_LOGSTD));
        t.w = __expf(fminf(t.w, MAX_LOGSTD));
    }
    float ex = __shfl_down_sync(0xffffffffu, t.x, 16);
    float ey = __shfl_down_sync(0xffffffffu, t.y, 16);
    float ez = __shfl_down_sync(0xffffffffu, t.z, 16);
    float ew = __shfl_down_sync(0xffffffffu, t.w, 16);
    if (lane < 16) {
        float4 ep = __ldg((const float4*)(eps + (size_t)d * COUT) + lane);
        float4 z;
        z.x = t.x + ep.x * ex;
        z.y = t.y + ep.y * ey;
        z.z = t.z + ep.z * ez;
        z.w = t.w + ep.w * ew;
        ((float4*)(out + (size_t)d * COUT))[lane] = z;
    }
}

// ---------------------------------------------------------------- launch ----
extern "C" void kernel_launch(void* const* d_in, const int* in_sizes, int n_in,
                              void* d_out, int out_size) {
    const float* x   = (const float*)d_in[0];
    const void*  ei  = d_in[1];                         // [2, E] int32 OR int64
    const float* Wmu = (const float*)d_in[2];
    const float* bmu = (const float*)d_in[3];
    const float* Wls = (const float*)d_in[4];
    const float* bls = (const float*)d_in[5];
    const float* eps = (const float*)d_in[6];
    float*       out = (float*)d_out;

    const int N  = in_sizes[0] / CIN;
    const int E  = in_sizes[1] / 2;
    const int nb = (N + 255) / 256;

    k_detect   <<<1, 32>>>(ei, N);
    k_ecnt_init<<<nb, 256>>>(N);
    k_ecnt     <<<(E + 255) / 256, 256>>>(ei, E);
    k_bsum     <<<nb, 256>>>(N);
    k_pscan    <<<1, 1024>>>(nb);
    k_offsets  <<<nb, 256>>>(N, E);
    k_fill     <<<(E + 255) / 256, 256>>>(ei, E);
    k_gemm     <<<(N + BM - 1) / BM, 256>>>(x, Wmu, Wls, N);
    {
        long long threads = (long long)N * 32;
        int blocks = (int)((threads + 255) / 256);
        k_agg  <<<blocks, 256>>>(bmu, bls, eps, out, N);
    }
}

// round 6
// speedup vs baseline: 1.8698x; 1.2472x over previous
#include <cuda_runtime.h>
#include <cstdint>

#define CIN   128
#define CTOT  128   // mu(64) | logstd(64) fused
#define COUT  64
#define MAXN  100000
#define MAXE  3200000
#define MAX_LOGSTD 10.0f

// ---- scratch (static device allocs; runtime alloc is forbidden) ----
__device__ int    g_idx64;                              // 1 if edge_index is int64
__device__ int    g_ecnt[MAXN];                         // in-degree (edges only)
__device__ int    g_off [MAXN + 1];                     // CSR row offsets
__device__ int    g_cur [MAXN];                         // fill cursors
__device__ int    g_part[1024];                         // block partial sums
__device__ int    g_csr [MAXE];                         // CSR src ids
__device__ float  g_dinv[MAXN];
__device__ float4 g_h4  [(size_t)MAXN * (CTOT / 4)];    // h (UNscaled)

// ------------------------------------------------------- dtype detection ----
__global__ void k_detect(const void* __restrict__ ei, int N) {
    if (threadIdx.x != 0 || blockIdx.x != 0) return;
    const long long* p = (const long long*)ei;
    int is64 = 1;
    #pragma unroll
    for (int i = 0; i < 16; i++) {
        long long v = p[i];
        if (v < 0 || v >= (long long)N) { is64 = 0; break; }
    }
    g_idx64 = is64;
}

__device__ __forceinline__ int load_idx(const void* __restrict__ base, long long i) {
    return g_idx64 ? (int)((const long long*)base)[i] : ((const int*)base)[i];
}

// ---------------------------------------------------- degree + CSR build ----
__global__ void k_ecnt(const void* __restrict__ ei, int E) {
    int i = blockIdx.x * blockDim.x + threadIdx.x;
    if (i < E) atomicAdd(&g_ecnt[load_idx(ei, (long long)E + i)], 1);
}

__global__ void k_bsum(int N) {
    __shared__ int s[256];
    int i = blockIdx.x * 256 + threadIdx.x;
    s[threadIdx.x] = (i < N) ? g_ecnt[i] : 0;
    __syncthreads();
    for (int st = 128; st > 0; st >>= 1) {
        if (threadIdx.x < st) s[threadIdx.x] += s[threadIdx.x + st];
        __syncthreads();
    }
    if (threadIdx.x == 0) g_part[blockIdx.x] = s[0];
}

__global__ void k_pscan(int nb) {
    __shared__ int s[1024];
    int t = threadIdx.x;
    s[t] = (t < nb) ? g_part[t] : 0;
    __syncthreads();
    for (int st = 1; st < 1024; st <<= 1) {
        int v = (t >= st) ? s[t - st] : 0;
        __syncthreads();
        s[t] += v;
        __syncthreads();
    }
    if (t < nb) g_part[t] = (t == 0) ? 0 : s[t - 1];   // exclusive
}

__global__ void k_offsets(int N, int E) {
    __shared__ int s[256];
    int i = blockIdx.x * 256 + threadIdx.x;
    int t = threadIdx.x;
    int c = (i < N) ? g_ecnt[i] : 0;
    s[t] = c;
    __syncthreads();
    for (int st = 1; st < 256; st <<= 1) {
        int v = (t >= st) ? s[t - st] : 0;
        __syncthreads();
        s[t] += v;
        __syncthreads();
    }
    if (i < N) {
        int off = g_part[blockIdx.x] + s[t] - c;   // exclusive
        g_off[i] = off;
        g_cur[i] = off;
        g_dinv[i] = rsqrtf((float)(1 + c));        // +1 self-loop
        if (i == N - 1) g_off[N] = E;
    }
}

__global__ void k_fill(const void* __restrict__ ei, int E) {
    int i = blockIdx.x * blockDim.x + threadIdx.x;
    if (i < E) {
        int sN = load_idx(ei, i);
        int d  = load_idx(ei, (long long)E + i);
        int slot = atomicAdd(&g_cur[d], 1);
        g_csr[slot] = sN;
    }
}

// ---------------------------------------------------------- tf32 helpers ----
__device__ __forceinline__ uint32_t f2tf32(float f) {
    uint32_t r;
    asm("cvt.rna.tf32.f32 %0, %1;" : "=r"(r) : "f"(f));
    return r;
}
__device__ __forceinline__ void split_tf32(float f, uint32_t& hi, uint32_t& lo) {
    hi = f2tf32(f);
    lo = f2tf32(f - __uint_as_float(hi));
}
__device__ __forceinline__ void mma_tf32(float c[4], const uint32_t a[4],
                                         uint32_t b0, uint32_t b1) {
    asm volatile(
        "mma.sync.aligned.m16n8k8.row.col.f32.tf32.tf32.f32 "
        "{%0,%1,%2,%3}, {%4,%5,%6,%7}, {%8,%9}, {%0,%1,%2,%3};"
        : "+f"(c[0]), "+f"(c[1]), "+f"(c[2]), "+f"(c[3])
        : "r"(a[0]), "r"(a[1]), "r"(a[2]), "r"(a[3]), "r"(b0), "r"(b1));
}

// ------------------------------------------------------------- tf32 GEMM ----
// h[n,0:64] = x[n,:] @ W_mu ; h[n,64:128] = x[n,:] @ W_ls  (UNscaled)
// CTA: 128 rows x 128 cols. 8 warps in 4x2: warp does 32 rows x 64 cols.
// 3-term split tf32 (hi/lo) => ~fp32 accuracy on tensor pipe.
#define AS_S 36    // As row stride (floats): 36%32=4 -> conflict-free a-frags
#define WS_S 136   // Ws row stride (floats): 136%32=8 -> conflict-free b-frags

__global__ __launch_bounds__(256)
void k_gemm_tf32(const float* __restrict__ x,
                 const float* __restrict__ Wmu,
                 const float* __restrict__ Wls, int N) {
    __shared__ float As[128][AS_S];
    __shared__ float Ws[32][WS_S];

    const int tid  = threadIdx.x;
    const int lane = tid & 31, wid = tid >> 5;
    const int m0   = (wid >> 1) * 32;        // warp row base (0/32/64/96)
    const int n0   = (wid & 1) * 64;         // warp col base (0/64)
    const int gid  = lane >> 2, tig = lane & 3;
    const int rowb = blockIdx.x * 128;

    float c[2][8][4];
    #pragma unroll
    for (int mt = 0; mt < 2; mt++)
        #pragma unroll
        for (int nt = 0; nt < 8; nt++)
            #pragma unroll
            for (int q = 0; q < 4; q++) c[mt][nt][q] = 0.f;

    for (int kt = 0; kt < CIN; kt += 32) {
        // x tile: 128 rows x 32 cols = 1024 float4
        #pragma unroll
        for (int idx = tid; idx < 1024; idx += 256) {
            int r = idx >> 3, j = idx & 7;
            int n = rowb + r;
            float4 v = (n < N)
                ? __ldg((const float4*)(x + (size_t)n * CIN + kt) + j)
                : make_float4(0.f, 0.f, 0.f, 0.f);
            *(float4*)&As[r][j * 4] = v;
        }
        // W tile: 32 k-rows x 128 cols (mu | ls)
        #pragma unroll
        for (int idx = tid; idx < 1024; idx += 256) {
            int kk = idx >> 5, j = idx & 31;
            float4 v = (j < 16) ? __ldg((const float4*)Wmu + (kt + kk) * 16 + j)
                                : __ldg((const float4*)Wls + (kt + kk) * 16 + (j - 16));
            *(float4*)&Ws[kk][j * 4] = v;
        }
        __syncthreads();

        #pragma unroll
        for (int ks = 0; ks < 32; ks += 8) {
            // A fragments (2 m-tiles), hi/lo split
            uint32_t ahi[2][4], alo[2][4];
            #pragma unroll
            for (int mt = 0; mt < 2; mt++) {
                int r0 = m0 + 16 * mt + gid;
                split_tf32(As[r0    ][ks + tig    ], ahi[mt][0], alo[mt][0]);
                split_tf32(As[r0 + 8][ks + tig    ], ahi[mt][1], alo[mt][1]);
                split_tf32(As[r0    ][ks + tig + 4], ahi[mt][2], alo[mt][2]);
                split_tf32(As[r0 + 8][ks + tig + 4], ahi[mt][3], alo[mt][3]);
            }
            #pragma unroll
            for (int nt = 0; nt < 8; nt++) {
                int cb = n0 + nt * 8 + gid;
                uint32_t bhi0, blo0, bhi1, blo1;
                split_tf32(Ws[ks + tig    ][cb], bhi0, blo0);
                split_tf32(Ws[ks + tig + 4][cb], bhi1, blo1);
                #pragma unroll
                for (int mt = 0; mt < 2; mt++) {
                    mma_tf32(c[mt][nt], ahi[mt], bhi0, bhi1);
                    mma_tf32(c[mt][nt], alo[mt], bhi0, bhi1);
                    mma_tf32(c[mt][nt], ahi[mt], blo0, blo1);
                }
            }
        }
        __syncthreads();
    }

    // epilogue: store h (unscaled). c0,c1 -> (row, col..col+1); c2,c3 -> row+8
    float* gh = (float*)g_h4;
    #pragma unroll
    for (int mt = 0; mt < 2; mt++) {
        #pragma unroll
        for (int nt = 0; nt < 8; nt++) {
            int row = rowb + m0 + 16 * mt + gid;
            int col = n0 + nt * 8 + 2 * tig;
            if (row < N)
                *(float2*)(gh + (size_t)row * CTOT + col) =
                    make_float2(c[mt][nt][0], c[mt][nt][1]);
            if (row + 8 < N)
                *(float2*)(gh + (size_t)(row + 8) * CTOT + col) =
                    make_float2(c[mt][nt][2], c[mt][nt][3]);
        }
    }
}

// --------------------------------------- aggregate + finalize (warp/node) ----
// lane L owns float4 #L. lanes 0-15: mu, 16-31: logstd.
// acc = h[d]*dinv[d] + sum_s h[s]*dinv[s];  t = acc*dinv[d] + bias
__global__ __launch_bounds__(256)
void k_agg(const float* __restrict__ bmu, const float* __restrict__ bls,
           const float* __restrict__ eps, float* __restrict__ out, int N) {
    int lane = threadIdx.x & 31;
    int d    = (blockIdx.x * blockDim.x + threadIdx.x) >> 5;
    if (d >= N) return;

    float di = g_dinv[d];
    float4 a = g_h4[(size_t)d * 32 + lane];        // self-loop seed
    a.x *= di; a.y *= di; a.z *= di; a.w *= di;

    int j   = g_off[d];
    int end = g_off[d + 1];
    for (; j + 1 < end; j += 2) {
        int s0 = g_csr[j], s1 = g_csr[j + 1];
        float w0 = __ldg(&g_dinv[s0]), w1 = __ldg(&g_dinv[s1]);
        float4 v0 = __ldg(&g_h4[(size_t)s0 * 32 + lane]);
        float4 v1 = __ldg(&g_h4[(size_t)s1 * 32 + lane]);
        a.x += v0.x * w0 + v1.x * w1; a.y += v0.y * w0 + v1.y * w1;
        a.z += v0.z * w0 + v1.z * w1; a.w += v0.w * w0 + v1.w * w1;
    }
    if (j < end) {
        int s = g_csr[j];
        float w = __ldg(&g_dinv[s]);
        float4 v = __ldg(&g_h4[(size_t)s * 32 + lane]);
        a.x += v.x * w; a.y += v.y * w; a.z += v.z * w; a.w += v.w * w;
    }

    float4 b = (lane < 16) ? __ldg((const float4*)bmu + lane)
                           : __ldg((const float4*)bls + (lane - 16));
    float4 t;
    t.x = a.x * di + b.x; t.y = a.y * di + b.y;
    t.z = a.z * di + b.z; t.w = a.w * di + b.w;
    if (lane >= 16) {
        t.x = __expf(fminf(t.x, MAX_LOGSTD));
        t.y = __expf(fminf(t.y, MAX_LOGSTD));
        t.z = __expf(fminf(t.z, MAX_LOGSTD));
        t.w = __expf(fminf(t.w, MAX_LOGSTD));
    }
    float ex = __shfl_down_sync(0xffffffffu, t.x, 16);
    float ey = __shfl_down_sync(0xffffffffu, t.y, 16);
    float ez = __shfl_down_sync(0xffffffffu, t.z, 16);
    float ew = __shfl_down_sync(0xffffffffu, t.w, 16);
    if (lane < 16) {
        float4 ep = __ldg((const float4*)(eps + (size_t)d * COUT) + lane);
        float4 z;
        z.x = t.x + ep.x * ex;
        z.y = t.y + ep.y * ey;
        z.z = t.z + ep.z * ez;
        z.w = t.w + ep.w * ew;
        ((float4*)(out + (size_t)d * COUT))[lane] = z;
    }
}

// ---------------------------------------------------------------- launch ----
extern "C" void kernel_launch(void* const* d_in, const int* in_sizes, int n_in,
                              void* d_out, int out_size) {
    const float* x   = (const float*)d_in[0];
    const void*  ei  = d_in[1];                         // [2, E] int32 OR int64
    const float* Wmu = (const float*)d_in[2];
    const float* bmu = (const float*)d_in[3];
    const float* Wls = (const float*)d_in[4];
    const float* bls = (const float*)d_in[5];
    const float* eps = (const float*)d_in[6];
    float*       out = (float*)d_out;

    const int N  = in_sizes[0] / CIN;
    const int E  = in_sizes[1] / 2;
    const int nb = (N + 255) / 256;

    void* ecnt_ptr = nullptr;
    cudaGetSymbolAddress(&ecnt_ptr, g_ecnt);

    // GEMM is independent of the CSR chain (dinv applied in k_agg)
    k_gemm_tf32<<<(N + 127) / 128, 256>>>(x, Wmu, Wls, N);

    k_detect   <<<1, 32>>>(ei, N);
    cudaMemsetAsync(ecnt_ptr, 0, (size_t)N * sizeof(int));
    k_ecnt     <<<(E + 255) / 256, 256>>>(ei, E);
    k_bsum     <<<nb, 256>>>(N);
    k_pscan    <<<1, 1024>>>(nb);
    k_offsets  <<<nb, 256>>>(N, E);
    k_fill     <<<(E + 255) / 256, 256>>>(ei, E);
    {
        long long threads = (long long)N * 32;
        int blocks = (int)((threads + 255) / 256);
        k_agg  <<<blocks, 256>>>(bmu, bls, eps, out, N);
    }
}